// round 17
// baseline (speedup 1.0000x reference)
#include <cuda_runtime.h>
#include <cuda_bf16.h>

#define NN 10000
#define NE 640000
#define DD 128
#define ND (NN * DD)

// ---------------- device scratch (no allocations allowed) ----------------
__device__ int   g_is64;        // 1 if src/dst are int64, 0 if int32
__device__ int   g_indeg[NN];
__device__ int   g_outdeg[NN];
__device__ int   g_fill[NN];
__device__ int   g_row_start[NN + 1];
__device__ float g_norm_src[NN];
__device__ float g_norm_dst[NN];
__device__ int2  g_edge[NE];    // (src node, norm_src bits) per edge, grouped by dst
__device__ uint2 g_x16[NN * 32]; // bf16 copy of previous layer output (128 bf16/row)

__device__ __forceinline__ int edge_idx(const void* p, int e, int is64) {
    if (is64) return (int)((const long long*)p)[e];
    return ((const int*)p)[e];
}

// ---------------- detect dtype + zero counters (merged) ------------------
__global__ void detect_zero_kernel(const void* src) {
    int i = blockIdx.x * blockDim.x + threadIdx.x;
    if (i < NN) { g_indeg[i] = 0; g_outdeg[i] = 0; g_fill[i] = 0; }
    if (blockIdx.x == 0) {
        __shared__ int any_nonzero;
        if (threadIdx.x == 0) any_nonzero = 0;
        __syncthreads();
        const int* w = (const int*)src;
#pragma unroll
        for (int it = 0; it < 2; it++) {
            int idx = 2 * (threadIdx.x + it * 256) + 1;
            if (w[idx] != 0) any_nonzero = 1;
        }
        __syncthreads();
        if (threadIdx.x == 0) g_is64 = any_nonzero ? 0 : 1;
    }
}

__global__ void degrees_kernel(const void* __restrict__ src,
                               const void* __restrict__ dst) {
    int e = blockIdx.x * blockDim.x + threadIdx.x;
    int is64 = g_is64;
    if (e < NE) {
        int s = edge_idx(src, e, is64);
        int d = edge_idx(dst, e, is64);
        if ((unsigned)s < NN) atomicAdd(&g_outdeg[s], 1);
        if ((unsigned)d < NN) atomicAdd(&g_indeg[d], 1);
    }
}

// ---------------- norms + row_start scan (merged) -------------------------
__global__ void norms_scan_kernel() {
    int i = blockIdx.x * blockDim.x + threadIdx.x;
    if (i < NN) {
        g_norm_src[i] = rsqrtf(fmaxf((float)g_outdeg[i], 1.0f));
        g_norm_dst[i] = rsqrtf(fmaxf((float)g_indeg[i], 1.0f));
    }
    if (blockIdx.x == 0) {
        __shared__ int ssum[256];
        const int CH = 40;            // 256 * 40 = 10240 >= NN
        int t = threadIdx.x;
        int base = t * CH;
        int s = 0;
#pragma unroll 8
        for (int k = 0; k < CH; k++) {
            int idx = base + k;
            s += (idx < NN) ? g_indeg[idx] : 0;
        }
        ssum[t] = s;
        __syncthreads();
        for (int off = 1; off < 256; off <<= 1) {
            int add = (t >= off) ? ssum[t - off] : 0;
            __syncthreads();
            ssum[t] += add;
            __syncthreads();
        }
        int run = (t > 0) ? ssum[t - 1] : 0;
#pragma unroll 8
        for (int k = 0; k < CH; k++) {
            int idx = base + k;
            if (idx < NN) {
                g_row_start[idx] = run;
                run += g_indeg[idx];
            }
        }
        if (t == 255) g_row_start[NN] = ssum[255];
    }
}

__global__ void fill_kernel(const void* __restrict__ src,
                            const void* __restrict__ dst) {
    int e = blockIdx.x * blockDim.x + threadIdx.x;
    int is64 = g_is64;
    if (e < NE) {
        int d = edge_idx(dst, e, is64);
        int s = edge_idx(src, e, is64);
        if ((unsigned)d < NN && (unsigned)s < NN) {
            int pos = g_row_start[d] + atomicAdd(&g_fill[d], 1);
            g_edge[pos] = make_int2(s, __float_as_int(g_norm_src[s]));
        }
    }
}

// ================= fused layer kernel =====================================
// Block owns 64 output rows. Phase 1 (SpMM): 8 warps aggregate 8 rows each
// into smem Ar[64][129] (pad -> bank stride 1). Phase 2 (GEMM): 64x128x128
// from smem A and streamed W tiles; epilogue bias+ReLU, writes Y fp32 and
// g_x16 bf16 (for the next layer's gather).

// ---- gather macros ----
#define GATHER_FP32(E) Xv[(E).x * 32 + lane]
#define FMA4(A, V, NV) { (A).x += (V).x * (NV); (A).y += (V).y * (NV); \
                         (A).z += (V).z * (NV); (A).w += (V).w * (NV); }

__device__ __forceinline__ float4 bf16_to_f4(uint2 v) {
    float2 lo = __bfloat1622float2(*(__nv_bfloat162*)&v.x);
    float2 hi = __bfloat1622float2(*(__nv_bfloat162*)&v.y);
    return make_float4(lo.x, lo.y, hi.x, hi.y);
}

#define GEMM_PHASE_AND_EPILOGUE()                                              \
    __syncthreads();                                                           \
    int tx = threadIdx.x & 15;                                                 \
    int ty = threadIdx.x >> 4;                                                 \
    int c0 = tx * 8;                                                           \
    float acc[4][8];                                                           \
    _Pragma("unroll") for (int i = 0; i < 4; i++)                              \
        _Pragma("unroll") for (int j = 0; j < 8; j++) acc[i][j] = 0.f;         \
    for (int kb = 0; kb < DD; kb += 16) {                                      \
        int kw = threadIdx.x >> 4;                                             \
        *(float4*)&Ws[kw][c0]     = *(const float4*)&W[(kb + kw) * DD + c0];   \
        *(float4*)&Ws[kw][c0 + 4] = *(const float4*)&W[(kb + kw) * DD + c0 + 4];\
        __syncthreads();                                                       \
        _Pragma("unroll") for (int kk = 0; kk < 16; kk++) {                    \
            int k = kb + kk;                                                   \
            float a0 = Ar[ty * 4 + 0][k];                                      \
            float a1 = Ar[ty * 4 + 1][k];                                      \
            float a2 = Ar[ty * 4 + 2][k];                                      \
            float a3 = Ar[ty * 4 + 3][k];                                      \
            float4 w0 = *(const float4*)&Ws[kk][c0];                           \
            float4 w1 = *(const float4*)&Ws[kk][c0 + 4];                       \
            acc[0][0] += a0*w0.x; acc[0][1] += a0*w0.y; acc[0][2] += a0*w0.z; acc[0][3] += a0*w0.w; \
            acc[0][4] += a0*w1.x; acc[0][5] += a0*w1.y; acc[0][6] += a0*w1.z; acc[0][7] += a0*w1.w; \
            acc[1][0] += a1*w0.x; acc[1][1] += a1*w0.y; acc[1][2] += a1*w0.z; acc[1][3] += a1*w0.w; \
            acc[1][4] += a1*w1.x; acc[1][5] += a1*w1.y; acc[1][6] += a1*w1.z; acc[1][7] += a1*w1.w; \
            acc[2][0] += a2*w0.x; acc[2][1] += a2*w0.y; acc[2][2] += a2*w0.z; acc[2][3] += a2*w0.w; \
            acc[2][4] += a2*w1.x; acc[2][5] += a2*w1.y; acc[2][6] += a2*w1.z; acc[2][7] += a2*w1.w; \
            acc[3][0] += a3*w0.x; acc[3][1] += a3*w0.y; acc[3][2] += a3*w0.z; acc[3][3] += a3*w0.w; \
            acc[3][4] += a3*w1.x; acc[3][5] += a3*w1.y; acc[3][6] += a3*w1.z; acc[3][7] += a3*w1.w; \
        }                                                                      \
        __syncthreads();                                                       \
    }                                                                          \
    float4 bias0 = *(const float4*)&b[c0];                                     \
    float4 bias1 = *(const float4*)&b[c0 + 4];                                 \
    _Pragma("unroll") for (int i = 0; i < 4; i++) {                            \
        int r = rb + ty * 4 + i;                                               \
        if (r < NN) {                                                          \
            float4 o0, o1;                                                     \
            o0.x = acc[i][0] + bias0.x; o0.y = acc[i][1] + bias0.y;            \
            o0.z = acc[i][2] + bias0.z; o0.w = acc[i][3] + bias0.w;            \
            o1.x = acc[i][4] + bias1.x; o1.y = acc[i][5] + bias1.y;            \
            o1.z = acc[i][6] + bias1.z; o1.w = acc[i][7] + bias1.w;            \
            if (relu) {                                                        \
                o0.x = fmaxf(o0.x, 0.f); o0.y = fmaxf(o0.y, 0.f);              \
                o0.z = fmaxf(o0.z, 0.f); o0.w = fmaxf(o0.w, 0.f);              \
                o1.x = fmaxf(o1.x, 0.f); o1.y = fmaxf(o1.y, 0.f);              \
                o1.z = fmaxf(o1.z, 0.f); o1.w = fmaxf(o1.w, 0.f);              \
            }                                                                  \
            *(float4*)&Y[r * DD + c0]     = o0;                                \
            *(float4*)&Y[r * DD + c0 + 4] = o1;                                \
            if (write16) {                                                     \
                __nv_bfloat162 p0 = __float22bfloat162_rn(make_float2(o0.x, o0.y)); \
                __nv_bfloat162 p1 = __float22bfloat162_rn(make_float2(o0.z, o0.w)); \
                __nv_bfloat162 p2 = __float22bfloat162_rn(make_float2(o1.x, o1.y)); \
                __nv_bfloat162 p3 = __float22bfloat162_rn(make_float2(o1.z, o1.w)); \
                uint2 pkA, pkB;                                                \
                pkA.x = *(unsigned*)&p0; pkA.y = *(unsigned*)&p1;              \
                pkB.x = *(unsigned*)&p2; pkB.y = *(unsigned*)&p3;              \
                g_x16[r * 32 + (c0 >> 2)]     = pkA;                           \
                g_x16[r * 32 + (c0 >> 2) + 1] = pkB;                           \
            }                                                                  \
        }                                                                      \
    }

// ---- layer 1: fp32 gather from x (zero-mean input; bf16 would not average down)
__global__ void __launch_bounds__(256) layer_fp32_kernel(
        const float* __restrict__ X, const float* __restrict__ W,
        const float* __restrict__ b, float* __restrict__ Y,
        int relu, int write16) {
    __shared__ float Ar[64][129];
    __shared__ float Ws[16][132];
    int wid = threadIdx.x >> 5;
    int lane = threadIdx.x & 31;
    int rb = blockIdx.x * 64;
    const float4* __restrict__ Xv = (const float4*)X;
    const int2*   __restrict__ Ev = g_edge;

    for (int rr = 0; rr < 8; rr++) {
        int lr = wid * 8 + rr;
        int r = rb + lr;
        float4 a0 = make_float4(0.f,0.f,0.f,0.f), a1 = a0, a2 = a0, a3 = a0;
        if (r < NN) {
            int j0 = g_row_start[r], j1 = g_row_start[r + 1];
            int j = j0;
            for (; j + 8 <= j1; j += 8) {
                int2 e0 = Ev[j+0], e1 = Ev[j+1], e2 = Ev[j+2], e3 = Ev[j+3];
                int2 e4 = Ev[j+4], e5 = Ev[j+5], e6 = Ev[j+6], e7 = Ev[j+7];
                float4 v0 = GATHER_FP32(e0), v1 = GATHER_FP32(e1);
                float4 v2 = GATHER_FP32(e2), v3 = GATHER_FP32(e3);
                float4 v4 = GATHER_FP32(e4), v5 = GATHER_FP32(e5);
                float4 v6 = GATHER_FP32(e6), v7 = GATHER_FP32(e7);
                FMA4(a0, v0, __int_as_float(e0.y)) FMA4(a1, v1, __int_as_float(e1.y))
                FMA4(a2, v2, __int_as_float(e2.y)) FMA4(a3, v3, __int_as_float(e3.y))
                FMA4(a0, v4, __int_as_float(e4.y)) FMA4(a1, v5, __int_as_float(e5.y))
                FMA4(a2, v6, __int_as_float(e6.y)) FMA4(a3, v7, __int_as_float(e7.y))
            }
            for (; j < j1; ++j) {
                int2 e = Ev[j];
                float4 v = GATHER_FP32(e);
                FMA4(a0, v, __int_as_float(e.y))
            }
            float nd = g_norm_dst[r];
            a0.x = (a0.x + a1.x + a2.x + a3.x) * nd;
            a0.y = (a0.y + a1.y + a2.y + a3.y) * nd;
            a0.z = (a0.z + a1.z + a2.z + a3.z) * nd;
            a0.w = (a0.w + a1.w + a2.w + a3.w) * nd;
        } else {
            a0 = make_float4(0.f,0.f,0.f,0.f);
        }
        Ar[lr][4*lane+0] = a0.x;
        Ar[lr][4*lane+1] = a0.y;
        Ar[lr][4*lane+2] = a0.z;
        Ar[lr][4*lane+3] = a0.w;
    }
    GEMM_PHASE_AND_EPILOGUE()
}

// ---- layers 2-6: bf16 gather (ReLU inputs: quantization noise averages down)
__global__ void __launch_bounds__(256) layer_bf16_kernel(
        const float* __restrict__ W, const float* __restrict__ b,
        float* __restrict__ Y, int relu, int write16) {
    __shared__ float Ar[64][129];
    __shared__ float Ws[16][132];
    int wid = threadIdx.x >> 5;
    int lane = threadIdx.x & 31;
    int rb = blockIdx.x * 64;
    const uint2* __restrict__ Xv = g_x16;
    const int2*  __restrict__ Ev = g_edge;

    for (int rr = 0; rr < 8; rr++) {
        int lr = wid * 8 + rr;
        int r = rb + lr;
        float4 a0 = make_float4(0.f,0.f,0.f,0.f), a1 = a0, a2 = a0, a3 = a0;
        if (r < NN) {
            int j0 = g_row_start[r], j1 = g_row_start[r + 1];
            int j = j0;
            for (; j + 8 <= j1; j += 8) {
                int2 e0 = Ev[j+0], e1 = Ev[j+1], e2 = Ev[j+2], e3 = Ev[j+3];
                int2 e4 = Ev[j+4], e5 = Ev[j+5], e6 = Ev[j+6], e7 = Ev[j+7];
                uint2 u0 = Xv[e0.x * 32 + lane], u1 = Xv[e1.x * 32 + lane];
                uint2 u2 = Xv[e2.x * 32 + lane], u3 = Xv[e3.x * 32 + lane];
                uint2 u4 = Xv[e4.x * 32 + lane], u5 = Xv[e5.x * 32 + lane];
                uint2 u6 = Xv[e6.x * 32 + lane], u7 = Xv[e7.x * 32 + lane];
                FMA4(a0, bf16_to_f4(u0), __int_as_float(e0.y))
                FMA4(a1, bf16_to_f4(u1), __int_as_float(e1.y))
                FMA4(a2, bf16_to_f4(u2), __int_as_float(e2.y))
                FMA4(a3, bf16_to_f4(u3), __int_as_float(e3.y))
                FMA4(a0, bf16_to_f4(u4), __int_as_float(e4.y))
                FMA4(a1, bf16_to_f4(u5), __int_as_float(e5.y))
                FMA4(a2, bf16_to_f4(u6), __int_as_float(e6.y))
                FMA4(a3, bf16_to_f4(u7), __int_as_float(e7.y))
            }
            for (; j < j1; ++j) {
                int2 e = Ev[j];
                FMA4(a0, bf16_to_f4(Xv[e.x * 32 + lane]), __int_as_float(e.y))
            }
            float nd = g_norm_dst[r];
            a0.x = (a0.x + a1.x + a2.x + a3.x) * nd;
            a0.y = (a0.y + a1.y + a2.y + a3.y) * nd;
            a0.z = (a0.z + a1.z + a2.z + a3.z) * nd;
            a0.w = (a0.w + a1.w + a2.w + a3.w) * nd;
        } else {
            a0 = make_float4(0.f,0.f,0.f,0.f);
        }
        Ar[lr][4*lane+0] = a0.x;
        Ar[lr][4*lane+1] = a0.y;
        Ar[lr][4*lane+2] = a0.z;
        Ar[lr][4*lane+3] = a0.w;
    }
    GEMM_PHASE_AND_EPILOGUE()
}

// ---------------- launch ----------------
extern "C" void kernel_launch(void* const* d_in, const int* in_sizes, int n_in,
                              void* d_out, int out_size) {
    const float* x   = (const float*)d_in[0];
    const void*  src = d_in[1];   // int32 or int64 — detected on device
    const void*  dst = d_in[2];
    const float* W[6] = { (const float*)d_in[3], (const float*)d_in[5],
                          (const float*)d_in[7], (const float*)d_in[9],
                          (const float*)d_in[11], (const float*)d_in[13] };
    const float* B[6] = { (const float*)d_in[4], (const float*)d_in[6],
                          (const float*)d_in[8], (const float*)d_in[10],
                          (const float*)d_in[12], (const float*)d_in[14] };
    float* out = (float*)d_out;

    // output layout: (h6, h5, h4, h3, h2, h1)
    float* h[6];
    for (int i = 0; i < 6; i++) h[i] = out + (size_t)(5 - i) * ND;  // h[0]=h1 ... h[5]=h6

    // graph build (4 launches)
    detect_zero_kernel<<<(NN + 255) / 256, 256>>>(src);
    degrees_kernel<<<(NE + 255) / 256, 256>>>(src, dst);
    norms_scan_kernel<<<(NN + 255) / 256, 256>>>();
    fill_kernel<<<(NE + 255) / 256, 256>>>(src, dst);

    int layer_grid = (NN + 63) / 64;   // 157 blocks

    for (int layer = 0; layer < 6; layer++) {
        int relu = (layer < 5) ? 1 : 0;
        int write16 = (layer < 5) ? 1 : 0;
        if (layer == 0)
            layer_fp32_kernel<<<layer_grid, 256>>>(x, W[0], B[0], h[0], relu, write16);
        else
            layer_bf16_kernel<<<layer_grid, 256>>>(W[layer], B[layer], h[layer], relu, write16);
    }
}